// round 6
// baseline (speedup 1.0000x reference)
#include <cuda_runtime.h>
#include <cstdint>

// Problem constants
#define BB     64
#define SS     2048
#define INDIM  512
#define HH     512
#define CL     8            // cluster size (j-split of W_hh)
#define NCTA   128          // 16 clusters x 8 CTAs

typedef unsigned long long ull;

// ---------------- packed f32x2 helpers (FFMA2 path, sm_103a) ----------------
__device__ __forceinline__ void ffma2(ull& acc, ull a, ull b) {
    asm volatile("fma.rn.f32x2 %0, %1, %2, %0;" : "+l"(acc) : "l"(a), "l"(b));
}
__device__ __forceinline__ ull pack2(float x) {
    ull r; asm("mov.b64 %0, {%1, %1};" : "=l"(r) : "f"(x)); return r;
}
__device__ __forceinline__ float2 unpack2(ull v) {
    float2 r; asm("mov.b64 {%0, %1}, %2;" : "=f"(r.x), "=f"(r.y) : "l"(v)); return r;
}
__device__ __forceinline__ uint32_t smem_u32(const void* p) {
    uint32_t a;
    asm("{ .reg .u64 t; cvta.to.shared.u64 t, %1; cvt.u32.u64 %0, t; }" : "=r"(a) : "l"(p));
    return a;
}
__device__ __forceinline__ uint32_t mapa_rank(uint32_t laddr, uint32_t rank) {
    uint32_t r;
    asm("mapa.shared::cluster.u32 %0, %1, %2;" : "=r"(r) : "r"(laddr), "r"(rank));
    return r;
}
__device__ __forceinline__ void mbar_init(uint32_t mbar, uint32_t cnt) {
    asm volatile("mbarrier.init.shared.b64 [%0], %1;" :: "r"(mbar), "r"(cnt) : "memory");
}
__device__ __forceinline__ void mbar_arrive_expect_tx(uint32_t mbar, uint32_t tx) {
    asm volatile("mbarrier.arrive.expect_tx.shared.b64 _, [%0], %1;"
                 :: "r"(mbar), "r"(tx) : "memory");
}
__device__ __forceinline__ void mbar_wait_cluster(uint32_t mbar, uint32_t parity) {
    asm volatile(
        "{\n\t.reg .pred P;\n\t"
        "WL_%=:\n\t"
        "mbarrier.try_wait.parity.acquire.cluster.shared::cta.b64 P, [%0], %1, 0x989680;\n\t"
        "@!P bra WL_%=;\n\t}"
        :: "r"(mbar), "r"(parity) : "memory");
}
// remote smem store carrying complete_tx to the remote rank's mbarrier
__device__ __forceinline__ void st_async_b64(uint32_t raddr, ull v, uint32_t rmbar) {
    asm volatile("st.async.shared::cluster.mbarrier::complete_tx::bytes.b64 [%0], %1, [%2];"
                 :: "r"(raddr), "l"(v), "r"(rmbar) : "memory");
}

// ---------------- Phase 1: x_proj = inputs @ W_ih^T + b_ih ----------------
__global__ __launch_bounds__(256) void xproj_kernel(
    const float* __restrict__ A, const float* __restrict__ W,
    const float* __restrict__ bias, float* __restrict__ C) {
    __shared__ float As[16][132];
    __shared__ float Bs[16][132];

    const int tid = threadIdx.x;
    const int m0 = blockIdx.x * 128;
    const int n0 = blockIdx.y * 128;
    const int lr = tid >> 2;
    const int lk = (tid & 3) << 2;
    const int tx = tid & 15;
    const int ty = tid >> 4;

    ull acc[8][4];
#pragma unroll
    for (int i = 0; i < 8; i++)
#pragma unroll
        for (int j = 0; j < 4; j++) acc[i][j] = 0ull;

    for (int k0 = 0; k0 < INDIM; k0 += 16) {
        float4 a0 = *(const float4*)(A + (size_t)(m0 + lr) * INDIM + k0 + lk);
        float4 a1 = *(const float4*)(A + (size_t)(m0 + lr + 64) * INDIM + k0 + lk);
        float4 w0 = *(const float4*)(W + (size_t)(n0 + lr) * INDIM + k0 + lk);
        float4 w1 = *(const float4*)(W + (size_t)(n0 + lr + 64) * INDIM + k0 + lk);
        __syncthreads();
        As[lk + 0][lr] = a0.x; As[lk + 1][lr] = a0.y; As[lk + 2][lr] = a0.z; As[lk + 3][lr] = a0.w;
        As[lk + 0][lr + 64] = a1.x; As[lk + 1][lr + 64] = a1.y; As[lk + 2][lr + 64] = a1.z; As[lk + 3][lr + 64] = a1.w;
        Bs[lk + 0][lr] = w0.x; Bs[lk + 1][lr] = w0.y; Bs[lk + 2][lr] = w0.z; Bs[lk + 3][lr] = w0.w;
        Bs[lk + 0][lr + 64] = w1.x; Bs[lk + 1][lr + 64] = w1.y; Bs[lk + 2][lr + 64] = w1.z; Bs[lk + 3][lr + 64] = w1.w;
        __syncthreads();
#pragma unroll
        for (int k = 0; k < 16; k++) {
            float4 am0 = *(const float4*)&As[k][ty * 4];
            float4 am1 = *(const float4*)&As[k][64 + ty * 4];
            ulonglong2 bn0 = *(const ulonglong2*)&Bs[k][tx * 4];
            ulonglong2 bn1 = *(const ulonglong2*)&Bs[k][64 + tx * 4];
            float am[8] = {am0.x, am0.y, am0.z, am0.w, am1.x, am1.y, am1.z, am1.w};
#pragma unroll
            for (int i = 0; i < 8; i++) {
                ull ap = pack2(am[i]);
                ffma2(acc[i][0], ap, bn0.x);
                ffma2(acc[i][1], ap, bn0.y);
                ffma2(acc[i][2], ap, bn1.x);
                ffma2(acc[i][3], ap, bn1.y);
            }
        }
    }

    float4 bA = *(const float4*)(bias + n0 + tx * 4);
    float4 bBv = *(const float4*)(bias + n0 + 64 + tx * 4);
#pragma unroll
    for (int i = 0; i < 8; i++) {
        int m = m0 + ((i < 4) ? (ty * 4 + i) : (64 + ty * 4 + (i - 4)));
        float2 c0 = unpack2(acc[i][0]);
        float2 c1 = unpack2(acc[i][1]);
        float2 c2 = unpack2(acc[i][2]);
        float2 c3 = unpack2(acc[i][3]);
        float4 o0 = make_float4(c0.x + bA.x, c0.y + bA.y, c1.x + bA.z, c1.y + bA.w);
        float4 o1 = make_float4(c2.x + bBv.x, c2.y + bBv.y, c3.x + bBv.z, c3.y + bBv.w);
        *(float4*)(C + (size_t)m * HH + n0 + tx * 4) = o0;
        *(float4*)(C + (size_t)m * HH + n0 + 64 + tx * 4) = o1;
    }
}

// ---------------- Phase 2: warp-autonomous clustered scan ----------------
// Cluster of 8 CTAs = 4 batches in 2 groups. Warp w of rank r owns j in
// [64r+8w, 64r+8w+8); lane = (j, k-quarter). No __syncthreads in the loop:
// warps wait on the CTA's (group,slot) mbarrier, compute final outputs with
// shfl reduction, and scatter them with st.async.b64 directly from registers.
// hsp layout padded (+2 ull per 64 k-pairs) for conflict-free LDS.128.
__global__ __launch_bounds__(256, 1) __cluster_dims__(CL, 1, 1)
void rnn_scan_kernel(
    const float* __restrict__ h0, const float* __restrict__ W_hh,
    const float* __restrict__ b_hh, float* __restrict__ out, int write_hfinal) {
    __shared__ __align__(16) ull hsp[2][2][260][2];   // [grp][slot][kp(padded)][b]
    __shared__ ull mbars[4];                           // [grp*2 + slot]

    const int tid = threadIdx.x;
    const int w = tid >> 5;            // warp -> j-chunk [8w, 8w+8)
    const int l = tid & 31;
    uint32_t rank;
    asm("mov.u32 %0, %%cluster_ctarank;" : "=r"(rank));
    const int j0 = (int)rank * 64;
    const int b0 = (blockIdx.x >> 3) * 4;
    const int myj = 8 * w + (l & 7);   // local j within slice
    const int q = l >> 3;              // k-quarter (128 k each)
    const int gjl = j0 + myj;
    const int bl = (l >> 3) & 1;       // batch-within-group (valid for l<16)

    // ---- W row slice into registers: 64 k-pairs for (row gjl, quarter q) ----
    ull Wr[64];
    {
        const ull* wrow = (const ull*)(W_hh + (size_t)gjl * HH) + q * 64;
#pragma unroll
        for (int p = 0; p < 64; p++) Wr[p] = wrow[p];
    }
    const float bh = b_hh[gjl];

    // ---- init h slot 0 of both groups from h0 (padded layout) ----
#pragma unroll
    for (int g = 0; g < 2; g++) {
        float* hf = (float*)&hsp[g][0][0][0];
        for (int i = tid; i < 2 * HH; i += 256) {
            int b = i >> 9, k = i & 511, kp = k >> 1;
            hf[kp * 4 + (kp >> 6) * 4 + b * 2 + (k & 1)] =
                h0[(size_t)(b0 + 2 * g + b) * HH + k];
        }
    }

    const uint32_t mb_local = smem_u32(&mbars[0]);
    if (tid == 0) {
#pragma unroll
        for (int i = 0; i < 4; i++) {
            mbar_init(mb_local + 8 * i, 1);
            mbar_arrive_expect_tx(mb_local + 8 * i, 4096u);
        }
        asm volatile("fence.mbarrier_init.release.cluster;" ::: "memory");
    }
    __syncthreads();
    asm volatile("barrier.cluster.arrive.aligned;" ::: "memory");
    asm volatile("barrier.cluster.wait.aligned;" ::: "memory");

    // remote addresses
    const uint32_t hbase = smem_u32(&hsp[0][0][0][0]);
    uint32_t rh[CL], rm[CL];
#pragma unroll
    for (int r = 0; r < CL; r++) {
        rh[r] = mapa_rank(hbase, (uint32_t)r);
        rm[r] = mapa_rank(mb_local, (uint32_t)r);
    }
    // per-lane destination byte offset inside a (grp,slot) block (lanes < 16)
    const int kpl = 32 * (int)rank + 4 * w + ((l & 6) >> 1);
    const uint32_t dlane = (uint32_t)(kpl * 16 + (kpl >> 6) * 16 + bl * 8);
    const int rbase2 = (l & 1) * 4;    // even lanes -> ranks 0-3, odd -> 4-7

    const size_t obA = (size_t)(b0 + bl) * SS * HH + gjl;
    const size_t obB = (size_t)(b0 + 2 + bl) * SS * HH + gjl;
    float xpA = 0.f, xpB = 0.f, hlA = 0.f, hlB = 0.f;
    if (l < 16) { xpA = __ldcs(out + obA); xpB = __ldcs(out + obB); }
    uint32_t phA0 = 0, phA1 = 0, phB0 = 0, phB1 = 0;

    const int hoff = q * 130;          // ull offset of this lane's k-quarter

#define GSTEP(T, S, G, PH, XP, HL, OB)                                          \
  {                                                                             \
    if ((T) > 0) {                                                              \
      mbar_wait_cluster(mb_local + ((G) * 2 + (S)) * 8, PH);                    \
      PH ^= 1u;                                                                 \
      if (tid == 0) mbar_arrive_expect_tx(mb_local + ((G) * 2 + (S)) * 8, 4096u);\
    }                                                                           \
    const ull* hb = &hsp[G][S][0][0] + hoff;                                    \
    ull a0 = 0, a1 = 0, a2 = 0, a3 = 0;                                         \
    _Pragma("unroll")                                                           \
    for (int p = 0; p < 64; p += 2) {                                           \
      ulonglong2 hx = *(const ulonglong2*)(hb + p * 2);                         \
      ulonglong2 hy = *(const ulonglong2*)(hb + p * 2 + 2);                     \
      ffma2(a0, hx.x, Wr[p]);     ffma2(a1, hx.y, Wr[p]);                       \
      ffma2(a2, hy.x, Wr[p + 1]); ffma2(a3, hy.y, Wr[p + 1]);                   \
    }                                                                           \
    float2 f0 = unpack2(a0), f1 = unpack2(a1), f2 = unpack2(a2), f3 = unpack2(a3);\
    float s0 = (f0.x + f0.y) + (f2.x + f2.y);                                   \
    float s1 = (f1.x + f1.y) + (f3.x + f3.y);                                   \
    s0 += __shfl_xor_sync(0xffffffffu, s0, 8);                                  \
    s1 += __shfl_xor_sync(0xffffffffu, s1, 8);                                  \
    s0 += __shfl_xor_sync(0xffffffffu, s0, 16);                                 \
    s1 += __shfl_xor_sync(0xffffffffu, s1, 16);                                 \
    float pre = XP + (bl ? s1 : s0) + bh;                                       \
    float e = __expf(pre + pre);                                                \
    float hv = 1.f - __fdividef(2.f, e + 1.f);                                  \
    float hvn = __shfl_down_sync(0xffffffffu, hv, 1);                           \
    float hvp = __shfl_up_sync(0xffffffffu, hv, 1);                             \
    if ((T) + 1 < SS && l < 16) {                                               \
      ull v;                                                                    \
      if (l & 1) { asm("mov.b64 %0, {%1, %2};" : "=l"(v) : "f"(hvp), "f"(hv)); }\
      else       { asm("mov.b64 %0, {%1, %2};" : "=l"(v) : "f"(hv), "f"(hvn)); }\
      uint32_t so = (uint32_t)((G) * 8320 + ((S) ^ 1) * 4160) + dlane;          \
      uint32_t mo = (uint32_t)(((G) * 2 + ((S) ^ 1)) * 8);                      \
      _Pragma("unroll")                                                         \
      for (int r = 0; r < 4; r++)                                               \
        st_async_b64(rh[rbase2 + r] + so, v, rm[rbase2 + r] + mo);              \
    }                                                                           \
    if (l < 16) {                                                               \
      __stcs(out + OB + (size_t)(T) * HH, hv);                                  \
      HL = hv;                                                                  \
      if ((T) + 1 < SS) XP = __ldcs(out + OB + (size_t)((T) + 1) * HH);         \
    }                                                                           \
  }

    for (int t = 0; t < SS; t += 2) {
        GSTEP(t,     0, 0, phA0, xpA, hlA, obA);
        GSTEP(t,     0, 1, phB0, xpB, hlB, obB);
        GSTEP(t + 1, 1, 0, phA1, xpA, hlA, obA);
        GSTEP(t + 1, 1, 1, phB1, xpB, hlB, obB);
    }
#undef GSTEP

    if (write_hfinal && l < 16) {
        out[(size_t)BB * SS * HH + (size_t)(b0 + bl) * HH + gjl] = hlA;
        out[(size_t)BB * SS * HH + (size_t)(b0 + 2 + bl) * HH + gjl] = hlB;
    }
}

// ---------------- launch ----------------
extern "C" void kernel_launch(void* const* d_in, const int* in_sizes, int n_in,
                              void* d_out, int out_size) {
    const float* inputs = (const float*)d_in[0];   // [64, 2048, 512]
    const float* h0     = (const float*)d_in[1];   // [64, 512]
    const float* W_ih   = (const float*)d_in[2];   // [512, 512]
    const float* W_hh   = (const float*)d_in[3];   // [512, 512]
    const float* b_ih   = (const float*)d_in[4];   // [512]
    const float* b_hh   = (const float*)d_in[5];   // [512]
    float* out = (float*)d_out;

    // Phase 1: x_proj into the outs region of d_out (scan overwrites in place)
    dim3 g1((BB * SS) / 128, HH / 128, 1);
    xproj_kernel<<<g1, 256>>>(inputs, W_ih, b_ih, out);

    // Phase 2: 16 clusters of 8 CTAs, warp-autonomous mbarrier-paced scan
    long long need = (long long)BB * SS * HH + (long long)BB * HH;
    int wf = ((long long)out_size >= need) ? 1 : 0;
    rnn_scan_kernel<<<NCTA, 256>>>(h0, W_hh, b_hh, out, wf);
}